// round 16
// baseline (speedup 1.0000x reference)
#include <cuda_runtime.h>
#include <cuda_bf16.h>
#include <cstdint>

// auxiliary_loss: loss = 0.2 * (pos*sum_neg - neg*sum_pos) / (pos*neg)
// R16: R7/R11 optimum memory shape (single ld.global.nc.v8 per stream per
// iter, fused last-block finalize) at 512thr x 592 CTAs (4 CTAs/SM, same
// 2048 thr/SM). Block-shape axis: 128thr regressed (R14), 256thr = best so
// far; this tests the larger-block direction (fewer CTA-level overheads).

#define DETA 0.2

constexpr int RED_BLOCKS  = 592;    // 148 SMs * 4 CTAs
constexpr int RED_THREADS = 512;

// Scratch (__device__ globals; no allocation).
__device__ float        g_psum_all[RED_BLOCKS];
__device__ float        g_psum_pos[RED_BLOCKS];
__device__ int          g_pcnt[RED_BLOCKS];
__device__ unsigned int g_done = 0;   // reset by last block each call

__device__ __forceinline__ float warp_red_f(float v) {
    #pragma unroll
    for (int o = 16; o > 0; o >>= 1) v += __shfl_down_sync(0xffffffffu, v, o);
    return v;
}
__device__ __forceinline__ int warp_red_i(int v) {
    #pragma unroll
    for (int o = 16; o > 0; o >>= 1) v += __shfl_down_sync(0xffffffffu, v, o);
    return v;
}
__device__ __forceinline__ double warp_red_d(double v) {
    #pragma unroll
    for (int o = 16; o > 0; o >>= 1) v += __shfl_down_sync(0xffffffffu, v, o);
    return v;
}

// 256-bit vector loads (sm_103a). 32B aligned, read-only.
__device__ __forceinline__ void ldg256_f32(const float* p, float* v) {
    asm volatile("ld.global.nc.v8.f32 {%0,%1,%2,%3,%4,%5,%6,%7}, [%8];"
                 : "=f"(v[0]), "=f"(v[1]), "=f"(v[2]), "=f"(v[3]),
                   "=f"(v[4]), "=f"(v[5]), "=f"(v[6]), "=f"(v[7])
                 : "l"(p));
}
__device__ __forceinline__ void ldg256_s32(const int* p, int* v) {
    asm volatile("ld.global.nc.v8.b32 {%0,%1,%2,%3,%4,%5,%6,%7}, [%8];"
                 : "=r"(v[0]), "=r"(v[1]), "=r"(v[2]), "=r"(v[3]),
                   "=r"(v[4]), "=r"(v[5]), "=r"(v[6]), "=r"(v[7])
                 : "l"(p));
}

__global__ __launch_bounds__(RED_THREADS)
void fused_loss_kernel(const float* __restrict__ y,
                       const int*   __restrict__ lab,
                       int nvec8,            // n / 8
                       int tail,             // n % 8
                       float* __restrict__ out,
                       double n_total)
{
    // Two independent accumulator banks.
    float sa0 = 0.0f, sa1 = 0.0f, sp0 = 0.0f, sp1 = 0.0f;
    int   c0 = 0, c1 = 0;

    const int stride = gridDim.x * blockDim.x;   // 303104
    for (int i = blockIdx.x * blockDim.x + threadIdx.x; i < nvec8; i += stride) {
        float v[8];
        int   l[8];
        ldg256_f32(y   + (size_t)i * 8, v);
        ldg256_s32(lab + (size_t)i * 8, l);

        sa0 += (v[0] + v[1]) + (v[2] + v[3]);
        sa1 += (v[4] + v[5]) + (v[6] + v[7]);
        float p0 = 0.0f, p1 = 0.0f;
        if (l[0]) p0 += v[0];
        if (l[1]) p0 += v[1];
        if (l[2]) p0 += v[2];
        if (l[3]) p0 += v[3];
        if (l[4]) p1 += v[4];
        if (l[5]) p1 += v[5];
        if (l[6]) p1 += v[6];
        if (l[7]) p1 += v[7];
        sp0 += p0; sp1 += p1;
        c0  += (l[0] + l[1]) + (l[2] + l[3]);
        c1  += (l[4] + l[5]) + (l[6] + l[7]);
    }

    float sa = sa0 + sa1;
    float sp = sp0 + sp1;
    int   c  = c0 + c1;

    // Scalar tail (n % 8), handled once by block 0.
    if (blockIdx.x == 0 && (int)threadIdx.x < tail) {
        const float* yt = y   + (size_t)nvec8 * 8;
        const int*   lt = lab + (size_t)nvec8 * 8;
        float v = yt[threadIdx.x];
        int   l = lt[threadIdx.x];
        sa += v;
        if (l) { sp += v; c += 1; }
    }

    // Intra-block reduce
    sa = warp_red_f(sa);
    sp = warp_red_f(sp);
    c  = warp_red_i(c);

    __shared__ float s_sa[RED_THREADS / 32];
    __shared__ float s_sp[RED_THREADS / 32];
    __shared__ int   s_c [RED_THREADS / 32];
    __shared__ bool  s_last;
    int wid = threadIdx.x >> 5;
    int lid = threadIdx.x & 31;
    if (lid == 0) { s_sa[wid] = sa; s_sp[wid] = sp; s_c[wid] = c; }
    __syncthreads();

    if (wid == 0) {
        constexpr int NW = RED_THREADS / 32;
        float a = (lid < NW) ? s_sa[lid] : 0.0f;
        float p = (lid < NW) ? s_sp[lid] : 0.0f;
        int   k = (lid < NW) ? s_c [lid] : 0;
        a = warp_red_f(a);
        p = warp_red_f(p);
        k = warp_red_i(k);
        if (lid == 0) {
            g_psum_all[blockIdx.x] = a;
            g_psum_pos[blockIdx.x] = p;
            g_pcnt[blockIdx.x]     = k;
            __threadfence();
            unsigned int t = atomicAdd(&g_done, 1u);
            s_last = (t == (unsigned int)(gridDim.x - 1));
        }
    }
    __syncthreads();

    if (!s_last) return;

    // ---- Last block: finalize (partials L2-hot). Deterministic order. ----
    double dsa = 0.0, dsp = 0.0;
    long long dc = 0;
    for (int j = threadIdx.x; j < RED_BLOCKS; j += RED_THREADS) {
        dsa += (double)g_psum_all[j];
        dsp += (double)g_psum_pos[j];
        dc  += (long long)g_pcnt[j];
    }
    dsa = warp_red_d(dsa);
    dsp = warp_red_d(dsp);
    #pragma unroll
    for (int o = 16; o > 0; o >>= 1) dc += __shfl_down_sync(0xffffffffu, dc, o);

    __shared__ double d_sa[RED_THREADS / 32], d_sp[RED_THREADS / 32];
    __shared__ long long d_c[RED_THREADS / 32];
    if (lid == 0) { d_sa[wid] = dsa; d_sp[wid] = dsp; d_c[wid] = dc; }
    __syncthreads();

    if (threadIdx.x == 0) {
        double SA = 0.0, SP = 0.0;
        long long C = 0;
        #pragma unroll
        for (int j = 0; j < RED_THREADS / 32; j++) { SA += d_sa[j]; SP += d_sp[j]; C += d_c[j]; }

        double pos = (double)C;
        double neg = n_total - pos;
        bool valid = (pos > 0.0) && (neg > 0.0);
        double sum_neg = SA - SP;
        double denom = valid ? pos * neg : 1.0;
        double loss = DETA * (pos * sum_neg - neg * SP) / denom;
        out[0] = valid ? (float)loss : 0.0f;

        g_done = 0;   // reset for next graph replay
    }
}

extern "C" void kernel_launch(void* const* d_in, const int* in_sizes, int n_in,
                              void* d_out, int out_size)
{
    const float* y   = (const float*)d_in[0];
    const int*   lab = (const int*)d_in[1];
    int n = in_sizes[0];

    int nvec8 = n >> 3;
    int tail  = n & 7;

    fused_loss_kernel<<<RED_BLOCKS, RED_THREADS>>>(
        y, lab, nvec8, tail, (float*)d_out, (double)n);
}

// round 17
// speedup vs baseline: 1.0907x; 1.0907x over previous
#include <cuda_runtime.h>
#include <cuda_bf16.h>
#include <cstdint>

// auxiliary_loss: loss = 0.2 * (pos*sum_neg - neg*sum_pos) / (pos*neg)
// FINAL (= R7/R11/R13/R15, measured global optimum over 16 A/B rounds;
// this exact binary benched 47.6 / 47.6 / 48.4 / 48.6 / 48.7 us):
//  - single ld.global.nc.v8 per stream per iteration (MLP_p1=2), 256thr x
//    1184 CTA grid-stride. Swept and rejected: wider per-thread loads
//    (R2/R5/R8), chunked layout (R5), TMA-bulk pipeline (R6, neutral),
//    FFMA body (R9, neutral), L2::256B hint (R10, neutral), counted loop
//    (R12), 128-thr blocks (R14), 512-thr blocks (R16).
//  - fused last-block finalize in double removes the 2nd kernel launch.
//  - 5.8TB/s is the path-independent LTS/DRAM-bank roofline for this
//    dual-stream read scan: LDG.128, LDG.256, and TMA all plateau there.
//    DRAM% ~72 is the hardware ceiling for this access mix.

#define DETA 0.2

constexpr int RED_BLOCKS  = 1184;   // 148 SMs * 8 CTAs
constexpr int RED_THREADS = 256;

// Scratch (__device__ globals; no allocation).
__device__ float        g_psum_all[RED_BLOCKS];
__device__ float        g_psum_pos[RED_BLOCKS];
__device__ int          g_pcnt[RED_BLOCKS];
__device__ unsigned int g_done = 0;   // reset by last block each call

__device__ __forceinline__ float warp_red_f(float v) {
    #pragma unroll
    for (int o = 16; o > 0; o >>= 1) v += __shfl_down_sync(0xffffffffu, v, o);
    return v;
}
__device__ __forceinline__ int warp_red_i(int v) {
    #pragma unroll
    for (int o = 16; o > 0; o >>= 1) v += __shfl_down_sync(0xffffffffu, v, o);
    return v;
}
__device__ __forceinline__ double warp_red_d(double v) {
    #pragma unroll
    for (int o = 16; o > 0; o >>= 1) v += __shfl_down_sync(0xffffffffu, v, o);
    return v;
}

// 256-bit vector loads (sm_103a). 32B aligned, read-only.
__device__ __forceinline__ void ldg256_f32(const float* p, float* v) {
    asm volatile("ld.global.nc.v8.f32 {%0,%1,%2,%3,%4,%5,%6,%7}, [%8];"
                 : "=f"(v[0]), "=f"(v[1]), "=f"(v[2]), "=f"(v[3]),
                   "=f"(v[4]), "=f"(v[5]), "=f"(v[6]), "=f"(v[7])
                 : "l"(p));
}
__device__ __forceinline__ void ldg256_s32(const int* p, int* v) {
    asm volatile("ld.global.nc.v8.b32 {%0,%1,%2,%3,%4,%5,%6,%7}, [%8];"
                 : "=r"(v[0]), "=r"(v[1]), "=r"(v[2]), "=r"(v[3]),
                   "=r"(v[4]), "=r"(v[5]), "=r"(v[6]), "=r"(v[7])
                 : "l"(p));
}

__global__ __launch_bounds__(RED_THREADS)
void fused_loss_kernel(const float* __restrict__ y,
                       const int*   __restrict__ lab,
                       int nvec8,            // n / 8
                       int tail,             // n % 8
                       float* __restrict__ out,
                       double n_total)
{
    // Two independent accumulator banks.
    float sa0 = 0.0f, sa1 = 0.0f, sp0 = 0.0f, sp1 = 0.0f;
    int   c0 = 0, c1 = 0;

    const int stride = gridDim.x * blockDim.x;   // 303104
    for (int i = blockIdx.x * blockDim.x + threadIdx.x; i < nvec8; i += stride) {
        float v[8];
        int   l[8];
        ldg256_f32(y   + (size_t)i * 8, v);
        ldg256_s32(lab + (size_t)i * 8, l);

        sa0 += (v[0] + v[1]) + (v[2] + v[3]);
        sa1 += (v[4] + v[5]) + (v[6] + v[7]);
        float p0 = 0.0f, p1 = 0.0f;
        if (l[0]) p0 += v[0];
        if (l[1]) p0 += v[1];
        if (l[2]) p0 += v[2];
        if (l[3]) p0 += v[3];
        if (l[4]) p1 += v[4];
        if (l[5]) p1 += v[5];
        if (l[6]) p1 += v[6];
        if (l[7]) p1 += v[7];
        sp0 += p0; sp1 += p1;
        c0  += (l[0] + l[1]) + (l[2] + l[3]);
        c1  += (l[4] + l[5]) + (l[6] + l[7]);
    }

    float sa = sa0 + sa1;
    float sp = sp0 + sp1;
    int   c  = c0 + c1;

    // Scalar tail (n % 8), handled once by block 0.
    if (blockIdx.x == 0 && (int)threadIdx.x < tail) {
        const float* yt = y   + (size_t)nvec8 * 8;
        const int*   lt = lab + (size_t)nvec8 * 8;
        float v = yt[threadIdx.x];
        int   l = lt[threadIdx.x];
        sa += v;
        if (l) { sp += v; c += 1; }
    }

    // Intra-block reduce
    sa = warp_red_f(sa);
    sp = warp_red_f(sp);
    c  = warp_red_i(c);

    __shared__ float s_sa[RED_THREADS / 32];
    __shared__ float s_sp[RED_THREADS / 32];
    __shared__ int   s_c [RED_THREADS / 32];
    __shared__ bool  s_last;
    int wid = threadIdx.x >> 5;
    int lid = threadIdx.x & 31;
    if (lid == 0) { s_sa[wid] = sa; s_sp[wid] = sp; s_c[wid] = c; }
    __syncthreads();

    if (wid == 0) {
        constexpr int NW = RED_THREADS / 32;
        float a = (lid < NW) ? s_sa[lid] : 0.0f;
        float p = (lid < NW) ? s_sp[lid] : 0.0f;
        int   k = (lid < NW) ? s_c [lid] : 0;
        a = warp_red_f(a);
        p = warp_red_f(p);
        k = warp_red_i(k);
        if (lid == 0) {
            g_psum_all[blockIdx.x] = a;
            g_psum_pos[blockIdx.x] = p;
            g_pcnt[blockIdx.x]     = k;
            __threadfence();
            unsigned int t = atomicAdd(&g_done, 1u);
            s_last = (t == (unsigned int)(gridDim.x - 1));
        }
    }
    __syncthreads();

    if (!s_last) return;

    // ---- Last block: finalize (partials L2-hot). Deterministic order. ----
    double dsa = 0.0, dsp = 0.0;
    long long dc = 0;
    for (int j = threadIdx.x; j < RED_BLOCKS; j += RED_THREADS) {
        dsa += (double)g_psum_all[j];
        dsp += (double)g_psum_pos[j];
        dc  += (long long)g_pcnt[j];
    }
    dsa = warp_red_d(dsa);
    dsp = warp_red_d(dsp);
    #pragma unroll
    for (int o = 16; o > 0; o >>= 1) dc += __shfl_down_sync(0xffffffffu, dc, o);

    __shared__ double d_sa[RED_THREADS / 32], d_sp[RED_THREADS / 32];
    __shared__ long long d_c[RED_THREADS / 32];
    if (lid == 0) { d_sa[wid] = dsa; d_sp[wid] = dsp; d_c[wid] = dc; }
    __syncthreads();

    if (threadIdx.x == 0) {
        double SA = 0.0, SP = 0.0;
        long long C = 0;
        #pragma unroll
        for (int j = 0; j < RED_THREADS / 32; j++) { SA += d_sa[j]; SP += d_sp[j]; C += d_c[j]; }

        double pos = (double)C;
        double neg = n_total - pos;
        bool valid = (pos > 0.0) && (neg > 0.0);
        double sum_neg = SA - SP;
        double denom = valid ? pos * neg : 1.0;
        double loss = DETA * (pos * sum_neg - neg * SP) / denom;
        out[0] = valid ? (float)loss : 0.0f;

        g_done = 0;   // reset for next graph replay
    }
}

extern "C" void kernel_launch(void* const* d_in, const int* in_sizes, int n_in,
                              void* d_out, int out_size)
{
    const float* y   = (const float*)d_in[0];
    const int*   lab = (const int*)d_in[1];
    int n = in_sizes[0];

    int nvec8 = n >> 3;
    int tail  = n & 7;

    fused_loss_kernel<<<RED_BLOCKS, RED_THREADS>>>(
        y, lab, nvec8, tail, (float*)d_out, (double)n);
}